// round 16
// baseline (speedup 1.0000x reference)
#include <cuda_runtime.h>
#include <math.h>

#define NG 192
#define NTOT (NG * NG * NG)
#define BX 32
#define BY 4
#define BZ 4
#define TX (BX + 4)      // 36
#define TY (BY + 4)      // 8
#define TZ (BZ + 2)      // 6 : halo only on +z (forward offsets)
#define NROWS (TZ * TY)  // 48 tile rows
#define TILE (NROWS * TX)     // 1728

#define KN   500000.0f
#define MU   0.5f
#define EPSF 1e-4f
#define FULLMASK 0xffffffffu
#define BMASK 0x00FEFEFEu
#define LCAP (1 << 20)

// hit list + counter; statically zero; trailing reset kernel restores the
// zero invariant each run, so graph replays are deterministic.
__device__ int g_count;
__device__ int g_list[LCAP];

__device__ __forceinline__ int wrapN(int v) {
    if (v < 0) v += NG;
    if (v >= NG) v -= NG;
    return v;
}

// exact forward-offset check for one voxel; appends both endpoints of every
// true pair (d2 < two_d2, including d2 == 0 for friction) to the hit list.
__device__ __noinline__ void exact_forward_append(
    int gz, int gy, int gx, float two_d2,
    const float* __restrict__ xg, const float* __restrict__ yg,
    const float* __restrict__ zg)
{
    const int gidx = (gz * NG + gy) * NG + gx;
    const float px = xg[gidx], py = yg[gidx], pz = zg[gidx];
    #pragma unroll 1
    for (int oz = 0; oz <= 2; oz++) {
        #pragma unroll 1
        for (int oy = -2; oy <= 2; oy++) {
            if (oz == 0 && oy < 0) continue;
            #pragma unroll 1
            for (int ox = -2; ox <= 2; ox++) {
                if (oz == 0 && oy == 0 && ox < 1) continue;
                const int nidx = (wrapN(gz + oz) * NG + wrapN(gy + oy)) * NG
                               + wrapN(gx + ox);
                const float dx = px - xg[nidx];
                const float dy = py - yg[nidx];
                const float dz = pz - zg[nidx];
                const float d2 = fmaf(dz, dz, fmaf(dy, dy, dx * dx));
                if (d2 < two_d2) {
                    int i0 = atomicAdd(&g_count, 2);
                    if (i0 + 1 < LCAP) {
                        g_list[i0]     = gidx;
                        g_list[i0 + 1] = nidx;
                    }
                }
            }
        }
    }
}

// ---------------- Pass A: forward filter + coop zero-fill + list append -----
__global__ __launch_bounds__(BX * BY * BZ, 4)
void filter_kernel(const float* __restrict__ xg, const float* __restrict__ yg,
                   const float* __restrict__ zg,
                   const float* __restrict__ dptr, float* __restrict__ out)
{
    __shared__ unsigned qpk[TILE];   // bytes: (floor x, floor y, floor z, 0)

    const int lx = threadIdx.x, ly = threadIdx.y, lz = threadIdx.z;
    const int bx0 = blockIdx.x * BX;
    const int by0 = blockIdx.y * BY;
    const int bz0 = blockIdx.z * BZ;
    const int tid  = (lz * BY + ly) * BX + lx;
    const int wid  = tid >> 5;
    const int lane = tid & 31;

    // --- cooperative zero-fill of this block's 9 output regions (uint4) ---
    // 9 planes x 16 (z,y) rows x 32 floats = 1152 uint4 stores, 512 threads.
    {
        const float4 z4 = make_float4(0.f, 0.f, 0.f, 0.f);
        #pragma unroll
        for (int s = 0; s < 3; s++) {
            const int i = tid + s * 512;        // 0 .. 1535; valid < 1152
            if (i < 1152) {
                const int within = i & 7;       // uint4 within 128B row
                const int row = i >> 3;         // 0..143
                const int q   = row / 16;
                const int r16 = row % 16;
                const int zz  = r16 >> 2, yy = r16 & 3;
                float* p = out + q * NTOT
                         + ((bz0 + zz) * NG + (by0 + yy)) * NG + bx0
                         + within * 4;
                *(float4*)p = z4;
            }
        }
    }

    // --- warp-row halo key build: warp w fills tile rows 3w..3w+2 ---
    #pragma unroll 1
    for (int j = 0; j < 3; j++) {
        const int row = wid * 3 + j;            // 16 warps * 3 = 48 rows
        const int tz = row / TY, ty = row % TY;
        const int gz = wrapN(bz0 + tz);         // z halo: only above
        const int gy = wrapN(by0 + ty - 2);
        const float* rxp = xg + (gz * NG + gy) * NG;
        const float* ryp = yg + (gz * NG + gy) * NG;
        const float* rzp = zg + (gz * NG + gy) * NG;
        #pragma unroll
        for (int k = 0; k < 2; k++) {
            const int col = lane + 32 * k;
            if (col < TX) {
                const int gxx = wrapN(bx0 + col - 2);
                qpk[row * TX + col] =
                    (unsigned)(int)rxp[gxx] | ((unsigned)(int)ryp[gxx] << 8)
                    | ((unsigned)(int)rzp[gxx] << 16);
            }
        }
    }
    __syncthreads();

    const float d      = *dptr;
    const float two_d  = 2.0f * d;
    const float two_d2 = two_d * two_d;
    const bool  filter_ok = (two_d <= 1.0f);

    const int cz = lz, cy = ly + 2, cx = lx + 2;   // own z at tile tz = lz
    const int cidx = (cz * TY + cy) * TX + cx;
    const unsigned pq = qpk[cidx];

    const int gz = bz0 + lz, gy = by0 + ly, gx = bx0 + lx;
    const int gidx = (gz * NG + gy) * NG + gx;

    // ---- byte prefilter over the 62 lexicographically-forward offsets ----
    bool need = !filter_ok;
    if (filter_ok) {
        unsigned m0 = ~0u, m1 = ~0u, m2 = ~0u, m3 = ~0u;
        int k = 0;
        #pragma unroll
        for (int oz = 0; oz <= 2; oz++) {
            #pragma unroll
            for (int oy = -2; oy <= 2; oy++) {
                if (oz == 0 && oy < 0) continue;
                #pragma unroll
                for (int ox = -2; ox <= 2; ox++) {
                    if (oz == 0 && oy == 0 && ox < 1) continue;
                    const unsigned nq = qpk[cidx + (oz * TY + oy) * TX + ox];
                    const unsigned v = __vabsdiffu4(pq, nq) & BMASK;
                    const int lane4 = (k++) & 3;
                    if (lane4 == 0)      m0 = min(m0, v);
                    else if (lane4 == 1) m1 = min(m1, v);
                    else if (lane4 == 2) m2 = min(m2, v);
                    else                 m3 = min(m3, v);
                }
            }
        }
        need = (min(min(m0, m1), min(m2, m3)) == 0u);
    }

    // rare (~0.8% of warps): exact forward check; append true pairs
    if (__any_sync(FULLMASK, need)) {
        if (need) exact_forward_append(gz, gy, gx, two_d2, xg, yg, zg);
    }
}

// ---------------- Pass B: WARP-per-voxel exact evaluation -------------------
#define FBLK 256
#define FGRD 128
__global__ __launch_bounds__(FBLK)
void fixup_kernel(const float* __restrict__ xg, const float* __restrict__ yg,
                  const float* __restrict__ zg, const float* __restrict__ vxg,
                  const float* __restrict__ vyg, const float* __restrict__ vzg,
                  const float* __restrict__ dptr, float* __restrict__ out,
                  float eta)
{
    const int n = min(g_count, LCAP);
    if (n == 0) return;
    const int lane  = threadIdx.x & 31;
    const int warp  = (blockIdx.x * FBLK + threadIdx.x) >> 5;
    const int nwarp = (FGRD * FBLK) >> 5;
    const float two_d  = 2.0f * (*dptr);
    const float two_d2 = two_d * two_d;

    for (int i = warp; i < n; i += nwarp) {
        const int v  = g_list[i];
        const int gx = v % NG;
        const int r  = v / NG;
        const int gy = r % NG;
        const int gz = r / NG;

        const float px = xg[v], py = yg[v], pz = zg[v];
        const float pvx = vxg[v], pvy = vyg[v], pvz = vzg[v];

        float fxc = 0.f, fyc = 0.f, fzc = 0.f;
        float fxd = 0.f, fyd = 0.f, fzd = 0.f;

        // lane l handles offsets l, l+32, l+64, l+96 of 125 (self excluded
        // by the d2 > 0 guard). Independent loads -> MLP.
        #pragma unroll
        for (int kk = 0; kk < 4; kk++) {
            const int k = lane + 32 * kk;
            if (k < 125) {
                const int oz = k / 25 - 2;
                const int oy = (k / 5) % 5 - 2;
                const int ox = k % 5 - 2;
                const int nidx = (wrapN(gz + oz) * NG + wrapN(gy + oy)) * NG
                               + wrapN(gx + ox);
                const float dx = px - xg[nidx];
                const float dy = py - yg[nidx];
                const float dz = pz - zg[nidx];
                const float d2 = fmaf(dz, dz, fmaf(dy, dy, dx * dx));
                if (d2 < two_d2 && d2 > 0.0f) {
                    const float dist = sqrtf(d2);
                    const float safe = fmaxf(EPSF, dist);
                    const float inv  = 1.0f / safe;
                    const float coef = KN * (dist - two_d) * inv;
                    fxc += coef * dx;
                    fyc += coef * dy;
                    fzc += coef * dz;
                    const float dvx = pvx - vxg[nidx];
                    const float dvy = pvy - vyg[nidx];
                    const float dvz = pvz - vzg[nidx];
                    const float vn  = (dvx * dx + dvy * dy + dvz * dz) * inv;
                    const float c2  = eta * vn * inv;
                    fxd += c2 * dx;
                    fyd += c2 * dy;
                    fzd += c2 * dz;
                }
            }
        }

        #pragma unroll
        for (int s = 16; s > 0; s >>= 1) {
            fxc += __shfl_xor_sync(FULLMASK, fxc, s);
            fyc += __shfl_xor_sync(FULLMASK, fyc, s);
            fzc += __shfl_xor_sync(FULLMASK, fzc, s);
            fxd += __shfl_xor_sync(FULLMASK, fxd, s);
            fyd += __shfl_xor_sync(FULLMASK, fyd, s);
            fzd += __shfl_xor_sync(FULLMASK, fzd, s);
        }

        if (lane == 0) {
            // friction: only the LAST scan shift s=(2,2,2) survives, i.e.
            // neighbor offset (-2,-2,-2), against the fully accumulated sums.
            float frx = 0.f, fry = 0.f, frz = 0.f;
            const int nidx = (wrapN(gz - 2) * NG + wrapN(gy - 2)) * NG
                           + wrapN(gx - 2);
            const float dx = px - xg[nidx];
            const float dy = py - yg[nidx];
            const float dz = pz - zg[nidx];
            const float d2 = fmaf(dz, dz, fmaf(dy, dy, dx * dx));
            if (d2 < two_d2) {
                const float dvx = pvx - vxg[nidx];
                const float dvy = pvy - vyg[nidx];
                const float dvz = pvz - vzg[nidx];
                frx = -(fabsf(fabsf(MU * fyc) + fabsf(MU * fzc) - MU * fxd)
                        * dvx / fmaxf(EPSF, fabsf(dvx)));
                fry = -(fabsf(fabsf(MU * fxc) + fabsf(MU * fzc) - MU * fyd)
                        * dvy / fmaxf(EPSF, fabsf(dvy)));
                // NB: reference uses diffvy in the z-friction numerator (kept).
                frz = -(fabsf(fabsf(MU * fxc) + fabsf(MU * fyc) - MU * fzd)
                        * dvy / fmaxf(EPSF, fabsf(dvz)));
            }
            float* o = out + v;
            o[0 * NTOT] = fxc;
            o[1 * NTOT] = fyc;
            o[2 * NTOT] = fzc;
            o[3 * NTOT] = fxd;
            o[4 * NTOT] = fyd;
            o[5 * NTOT] = fzd;
            o[6 * NTOT] = frx;
            o[7 * NTOT] = fry;
            o[8 * NTOT] = frz;
        }
    }
}

// ---------------- Pass C: restore counter invariant for graph replay --------
__global__ void reset_kernel() {
    g_count = 0;
}

extern "C" void kernel_launch(void* const* d_in, const int* in_sizes, int n_in,
                              void* d_out, int out_size)
{
    const float* xg   = (const float*)d_in[0];
    const float* yg   = (const float*)d_in[1];
    const float* zg   = (const float*)d_in[2];
    const float* vxg  = (const float*)d_in[3];
    const float* vyg  = (const float*)d_in[4];
    const float* vzg  = (const float*)d_in[5];
    const float* dptr = (const float*)d_in[6];
    float* out = (float*)d_out;

    // ETA = 2*gamma*sqrt(KN), gamma = alpha/sqrt(alpha^2+1), alpha = -ln(0.7)/pi
    const double alpha = -log(0.7) / M_PI;
    const double gam   = alpha / sqrt(alpha * alpha + 1.0);
    const float  eta   = (float)(2.0 * gam * sqrt(500000.0));

    dim3 blockA(BX, BY, BZ);
    dim3 gridA(NG / BX, NG / BY, NG / BZ);
    filter_kernel<<<gridA, blockA>>>(xg, yg, zg, dptr, out);

    fixup_kernel<<<FGRD, FBLK>>>(xg, yg, zg, vxg, vyg, vzg, dptr, out, eta);

    reset_kernel<<<1, 1>>>();   // runs after fixup reads g_count
}

// round 17
// speedup vs baseline: 1.0932x; 1.0932x over previous
#include <cuda_runtime.h>
#include <math.h>

#define NG 192
#define NTOT (NG * NG * NG)
#define BX 32
#define BY 4
#define BZ 4
#define TX (BX + 4)      // 36
#define TY (BY + 4)      // 8
#define TZ (BZ + 2)      // 6 : halo only on +z (forward offsets)
#define TILE (TX * TY * TZ)   // 1728

#define KN   500000.0f
#define MU   0.5f
#define EPSF 1e-4f
#define FULLMASK 0xffffffffu
#define LCAP (1 << 20)

// hit list + counter; statically zero; trailing reset kernel restores the
// zero invariant each run, so graph replays are deterministic.
__device__ int g_count;
__device__ int g_list[LCAP];

__device__ __forceinline__ int wrapN(int v) {
    if (v < 0) v += NG;
    if (v >= NG) v -= NG;
    return v;
}

// exact forward-offset check for one voxel; appends both endpoints of every
// true pair (d2 < two_d2, including d2 == 0 for friction) to the hit list.
__device__ __noinline__ void exact_forward_append(
    int gz, int gy, int gx, float two_d2,
    const float* __restrict__ xg, const float* __restrict__ yg,
    const float* __restrict__ zg)
{
    const int gidx = (gz * NG + gy) * NG + gx;
    const float px = xg[gidx], py = yg[gidx], pz = zg[gidx];
    #pragma unroll 1
    for (int oz = 0; oz <= 2; oz++) {
        #pragma unroll 1
        for (int oy = -2; oy <= 2; oy++) {
            if (oz == 0 && oy < 0) continue;
            #pragma unroll 1
            for (int ox = -2; ox <= 2; ox++) {
                if (oz == 0 && oy == 0 && ox < 1) continue;
                const int nidx = (wrapN(gz + oz) * NG + wrapN(gy + oy)) * NG
                               + wrapN(gx + ox);
                const float dx = px - xg[nidx];
                const float dy = py - yg[nidx];
                const float dz = pz - zg[nidx];
                const float d2 = fmaf(dz, dz, fmaf(dy, dy, dx * dx));
                if (d2 < two_d2) {
                    int i0 = atomicAdd(&g_count, 2);
                    if (i0 + 1 < LCAP) {
                        g_list[i0]     = gidx;
                        g_list[i0 + 1] = nidx;
                    }
                }
            }
        }
    }
}

// ---------------- Pass A: forward-only SAD filter + zero-store + append -----
__global__ __launch_bounds__(BX * BY * BZ, 4)
void filter_kernel(const float* __restrict__ xg, const float* __restrict__ yg,
                   const float* __restrict__ zg,
                   const float* __restrict__ dptr, float* __restrict__ out)
{
    __shared__ unsigned qpk[TILE];   // bytes: (floor x, floor y, floor z, 0)

    const int lx = threadIdx.x, ly = threadIdx.y, lz = threadIdx.z;
    const int bx0 = blockIdx.x * BX;
    const int by0 = blockIdx.y * BY;
    const int bz0 = blockIdx.z * BZ;
    const int tid = (lz * BY + ly) * BX + lx;

    // halo key build: x,y wrap +-2; z only 0..+2 above (forward offsets)
    for (int idx = tid; idx < TILE; idx += BX * BY * BZ) {
        int tx = idx % TX;
        int r  = idx / TX;
        int ty = r % TY;
        int tz = r / TY;
        int gx = wrapN(bx0 + tx - 2);
        int gy = wrapN(by0 + ty - 2);
        int gz = wrapN(bz0 + tz);
        int g = (gz * NG + gy) * NG + gx;
        qpk[idx] = (unsigned)(int)xg[g] | ((unsigned)(int)yg[g] << 8)
                 | ((unsigned)(int)zg[g] << 16);
    }
    __syncthreads();

    const float d     = *dptr;
    const float two_d = 2.0f * d;
    const float two_d2 = two_d * two_d;
    // SAD-filter validity: |dx| < two_d <= 1 => per-axis floor diff <= 1
    // => sum of the three byte diffs <= 3. Conservative (no false negatives).
    const bool filter_ok = (two_d <= 1.0f);

    const int cz = lz, cy = ly + 2, cx = lx + 2;   // own z at tile tz = lz
    const int cidx = (cz * TY + cy) * TX + cx;
    const unsigned pq = qpk[cidx];

    const int gz = bz0 + lz, gy = by0 + ly, gx = bx0 + lx;
    const int gidx = (gz * NG + gy) * NG + gx;

    // ---- SAD prefilter over the 62 lexicographically-forward offsets ----
    // per offset: VABSDIFF4 (alu) + IDP.4A (fma pipe) + IMNMX (alu)
    bool need = !filter_ok;
    if (filter_ok) {
        unsigned m0 = ~0u, m1 = ~0u, m2 = ~0u, m3 = ~0u;
        int k = 0;
        #pragma unroll
        for (int oz = 0; oz <= 2; oz++) {
            #pragma unroll
            for (int oy = -2; oy <= 2; oy++) {
                if (oz == 0 && oy < 0) continue;
                #pragma unroll
                for (int ox = -2; ox <= 2; ox++) {
                    if (oz == 0 && oy == 0 && ox < 1) continue;
                    const unsigned nq = qpk[cidx + (oz * TY + oy) * TX + ox];
                    const unsigned df = __vabsdiffu4(pq, nq);
                    const unsigned s  = __dp4a(df, 0x01010101u, 0u); // byte sum
                    const int lane4 = (k++) & 3;
                    if (lane4 == 0)      m0 = min(m0, s);
                    else if (lane4 == 1) m1 = min(m1, s);
                    else if (lane4 == 2) m2 = min(m2, s);
                    else                 m3 = min(m3, s);
                }
            }
        }
        need = (min(min(m0, m1), min(m2, m3)) <= 3u);
    }

    // zero all nine outputs for every voxel; pass B overwrites true hits
    float* o = out + gidx;
    #pragma unroll
    for (int q = 0; q < 9; q++) o[q * NTOT] = 0.f;

    // rare (~1.8% of warps): exact forward check; append true pairs
    if (__any_sync(FULLMASK, need)) {
        if (need) exact_forward_append(gz, gy, gx, two_d2, xg, yg, zg);
    }
}

// ---------------- Pass B: WARP-per-voxel exact evaluation -------------------
#define FBLK 256
#define FGRD 128
__global__ __launch_bounds__(FBLK)
void fixup_kernel(const float* __restrict__ xg, const float* __restrict__ yg,
                  const float* __restrict__ zg, const float* __restrict__ vxg,
                  const float* __restrict__ vyg, const float* __restrict__ vzg,
                  const float* __restrict__ dptr, float* __restrict__ out,
                  float eta)
{
    const int n = min(g_count, LCAP);
    if (n == 0) return;
    const int lane  = threadIdx.x & 31;
    const int warp  = (blockIdx.x * FBLK + threadIdx.x) >> 5;
    const int nwarp = (FGRD * FBLK) >> 5;
    const float two_d  = 2.0f * (*dptr);
    const float two_d2 = two_d * two_d;

    for (int i = warp; i < n; i += nwarp) {
        const int v  = g_list[i];
        const int gx = v % NG;
        const int r  = v / NG;
        const int gy = r % NG;
        const int gz = r / NG;

        const float px = xg[v], py = yg[v], pz = zg[v];
        const float pvx = vxg[v], pvy = vyg[v], pvz = vzg[v];

        float fxc = 0.f, fyc = 0.f, fzc = 0.f;
        float fxd = 0.f, fyd = 0.f, fzd = 0.f;

        // lane l handles offsets l, l+32, l+64, l+96 of 125 (self excluded
        // by the d2 > 0 guard). Independent loads -> MLP.
        #pragma unroll
        for (int kk = 0; kk < 4; kk++) {
            const int k = lane + 32 * kk;
            if (k < 125) {
                const int oz = k / 25 - 2;
                const int oy = (k / 5) % 5 - 2;
                const int ox = k % 5 - 2;
                const int nidx = (wrapN(gz + oz) * NG + wrapN(gy + oy)) * NG
                               + wrapN(gx + ox);
                const float dx = px - xg[nidx];
                const float dy = py - yg[nidx];
                const float dz = pz - zg[nidx];
                const float d2 = fmaf(dz, dz, fmaf(dy, dy, dx * dx));
                if (d2 < two_d2 && d2 > 0.0f) {
                    const float dist = sqrtf(d2);
                    const float safe = fmaxf(EPSF, dist);
                    const float inv  = 1.0f / safe;
                    const float coef = KN * (dist - two_d) * inv;
                    fxc += coef * dx;
                    fyc += coef * dy;
                    fzc += coef * dz;
                    const float dvx = pvx - vxg[nidx];
                    const float dvy = pvy - vyg[nidx];
                    const float dvz = pvz - vzg[nidx];
                    const float vn  = (dvx * dx + dvy * dy + dvz * dz) * inv;
                    const float c2  = eta * vn * inv;
                    fxd += c2 * dx;
                    fyd += c2 * dy;
                    fzd += c2 * dz;
                }
            }
        }

        #pragma unroll
        for (int s = 16; s > 0; s >>= 1) {
            fxc += __shfl_xor_sync(FULLMASK, fxc, s);
            fyc += __shfl_xor_sync(FULLMASK, fyc, s);
            fzc += __shfl_xor_sync(FULLMASK, fzc, s);
            fxd += __shfl_xor_sync(FULLMASK, fxd, s);
            fyd += __shfl_xor_sync(FULLMASK, fyd, s);
            fzd += __shfl_xor_sync(FULLMASK, fzd, s);
        }

        if (lane == 0) {
            // friction: only the LAST scan shift s=(2,2,2) survives, i.e.
            // neighbor offset (-2,-2,-2), against the fully accumulated sums.
            float frx = 0.f, fry = 0.f, frz = 0.f;
            const int nidx = (wrapN(gz - 2) * NG + wrapN(gy - 2)) * NG
                           + wrapN(gx - 2);
            const float dx = px - xg[nidx];
            const float dy = py - yg[nidx];
            const float dz = pz - zg[nidx];
            const float d2 = fmaf(dz, dz, fmaf(dy, dy, dx * dx));
            if (d2 < two_d2) {
                const float dvx = pvx - vxg[nidx];
                const float dvy = pvy - vyg[nidx];
                const float dvz = pvz - vzg[nidx];
                frx = -(fabsf(fabsf(MU * fyc) + fabsf(MU * fzc) - MU * fxd)
                        * dvx / fmaxf(EPSF, fabsf(dvx)));
                fry = -(fabsf(fabsf(MU * fxc) + fabsf(MU * fzc) - MU * fyd)
                        * dvy / fmaxf(EPSF, fabsf(dvy)));
                // NB: reference uses diffvy in the z-friction numerator (kept).
                frz = -(fabsf(fabsf(MU * fxc) + fabsf(MU * fyc) - MU * fzd)
                        * dvy / fmaxf(EPSF, fabsf(dvz)));
            }
            float* o = out + v;
            o[0 * NTOT] = fxc;
            o[1 * NTOT] = fyc;
            o[2 * NTOT] = fzc;
            o[3 * NTOT] = fxd;
            o[4 * NTOT] = fyd;
            o[5 * NTOT] = fzd;
            o[6 * NTOT] = frx;
            o[7 * NTOT] = fry;
            o[8 * NTOT] = frz;
        }
    }
}

// ---------------- Pass C: restore counter invariant for graph replay --------
__global__ void reset_kernel() {
    g_count = 0;
}

extern "C" void kernel_launch(void* const* d_in, const int* in_sizes, int n_in,
                              void* d_out, int out_size)
{
    const float* xg   = (const float*)d_in[0];
    const float* yg   = (const float*)d_in[1];
    const float* zg   = (const float*)d_in[2];
    const float* vxg  = (const float*)d_in[3];
    const float* vyg  = (const float*)d_in[4];
    const float* vzg  = (const float*)d_in[5];
    const float* dptr = (const float*)d_in[6];
    float* out = (float*)d_out;

    // ETA = 2*gamma*sqrt(KN), gamma = alpha/sqrt(alpha^2+1), alpha = -ln(0.7)/pi
    const double alpha = -log(0.7) / M_PI;
    const double gam   = alpha / sqrt(alpha * alpha + 1.0);
    const float  eta   = (float)(2.0 * gam * sqrt(500000.0));

    dim3 blockA(BX, BY, BZ);
    dim3 gridA(NG / BX, NG / BY, NG / BZ);
    filter_kernel<<<gridA, blockA>>>(xg, yg, zg, dptr, out);

    fixup_kernel<<<FGRD, FBLK>>>(xg, yg, zg, vxg, vyg, vzg, dptr, out, eta);

    reset_kernel<<<1, 1>>>();   // runs after fixup reads g_count
}